// round 1
// baseline (speedup 1.0000x reference)
#include <cuda_runtime.h>
#include <math.h>
#include <stdint.h>

#define BB 32
#define NN 128
#define CD 128
#define PP 8128
#define RNDS 3

// ---------------- persistent device scratch (rewritten fully every launch) ----
__device__ float g_e   [(size_t)BB*NN*NN*CD];   // 256 MB edge features
__device__ float g_mbuf[(size_t)BB*NN*NN*CD];   // 256 MB messages (pre-reduction)
__device__ float g_h   [BB*NN*CD];
__device__ float g_hp  [BB*NN*512];             // [hwl | hvl | hwm | hvm]
__device__ float g_ms  [BB*NN*CD];
__device__ float g_gi  [BB*NN*384];
__device__ float g_gh  [BB*NN*384];
__device__ int   g_iu  [PP];
__device__ int   g_ju  [PP];

// ---------------- init kernels ------------------------------------------------
__global__ void k_init_e(const int* __restrict__ eids, const float* __restrict__ emb) {
    size_t t = (size_t)blockIdx.x * blockDim.x + threadIdx.x;   // over B*N*N*(CD/4)
    size_t total = (size_t)BB*NN*NN*(CD/4);
    if (t >= total) return;
    size_t edge = t >> 5;        // CD/4 = 32 float4 per edge
    int c4 = (int)(t & 31);
    int id = eids[edge];
    ((float4*)g_e)[t] = ((const float4*)emb)[id*(CD/4) + c4];
}

__global__ void k_copy_h(const float* __restrict__ nf) {
    int t = blockIdx.x * blockDim.x + threadIdx.x;
    if (t < BB*NN*CD/4) ((float4*)g_h)[t] = ((const float4*)nf)[t];
}

__global__ void k_init_pairs() {
    int t = blockIdx.x * blockDim.x + threadIdx.x;
    if (t >= NN*NN) return;
    int i = t / NN, j = t % NN;
    if (j > i) {
        int p = i*(NN-1) - i*(i-1)/2 + (j - i - 1);
        g_iu[p] = i; g_ju[p] = j;
    }
}

// ---------------- small row-block GEMM: C[rows,outC] = A[rows,128] @ W + bias --
__global__ void k_rowgemm(const float* __restrict__ A, const float* __restrict__ W,
                          const float* __restrict__ bias, float* __restrict__ C,
                          int outC, int ldC, int colOff) {
    __shared__ float sA[32*CD];
    int row0 = blockIdx.x * 32;
    for (int t = threadIdx.x; t < 32*CD; t += blockDim.x)
        sA[t] = A[(size_t)row0*CD + t];
    __syncthreads();
    int col = threadIdx.x;
    if (col >= outC) return;
    float acc[32];
#pragma unroll
    for (int r = 0; r < 32; ++r) acc[r] = 0.f;
    for (int c = 0; c < CD; ++c) {
        float w = W[c*outC + col];
#pragma unroll
        for (int r = 0; r < 32; ++r) acc[r] = fmaf(sA[r*CD + c], w, acc[r]);
    }
    float bv = bias ? bias[col] : 0.f;
    for (int r = 0; r < 32; ++r)
        C[(size_t)(row0 + r)*ldC + colOff + col] = acc[r] + bv;
}

// ---------------- shared 8x8 register-tile GEMM core ---------------------------
template<int LDA, int LDB, int KSTEPS>
__device__ __forceinline__ void gemm_tile(const float* __restrict__ pA,   // &sA[r0*LDA + cbeg]
                                          const float* __restrict__ pB,   // &sB[0*LDB + k0]
                                          float acc[8][8]) {
#pragma unroll 2
    for (int c0 = 0; c0 < KSTEPS; c0 += 4) {
        float4 a4[8];
#pragma unroll
        for (int r = 0; r < 8; ++r)
            a4[r] = *(const float4*)(pA + r*LDA + c0);
#pragma unroll
        for (int cs = 0; cs < 4; ++cs) {
            float4 b0 = *(const float4*)(pB + (size_t)(c0 + cs)*LDB);
            float4 b1 = *(const float4*)(pB + (size_t)(c0 + cs)*LDB + 4);
            float bb[8] = {b0.x,b0.y,b0.z,b0.w,b1.x,b1.y,b1.z,b1.w};
#pragma unroll
            for (int r = 0; r < 8; ++r) {
                float av = (cs==0) ? a4[r].x : (cs==1) ? a4[r].y : (cs==2) ? a4[r].z : a4[r].w;
#pragma unroll
                for (int c = 0; c < 8; ++c)
                    acc[r][c] = fmaf(av, bb[c], acc[r][c]);
            }
        }
    }
}

// ---------------- the fused per-edge-row kernel (hot loop) ---------------------
// CTA = (b, i). E tile 128x128 in smem; 4 GEMMs:
//  1) E@Wl_e -> z -> adj -> s          2) E@Wm_e -> m (masked*scaled) -> sM, g_mbuf
//  3) E@Wu_e (+)  4) sM@Wu_m  -> e_new = pm ? relu(.+bu) : e_old
#define EDGE_SMEM_FLOATS (16384*3 + 2048 + 128)
__global__ __launch_bounds__(256, 1)
void k_edge(const float* __restrict__ Wl_e, const float* __restrict__ Wm_e,
            const float* __restrict__ Wu_e, const float* __restrict__ Wu_m,
            const float* __restrict__ wl2,  const float* __restrict__ bl2,
            const float* __restrict__ bu,   const int* __restrict__ ev)
{
    extern __shared__ float sm[];
    float* sE    = sm;
    float* sW    = sm + 16384;
    float* sM    = sm + 32768;
    float* sPart = sm + 49152;   // [128][16] adj partials (deterministic reduce)
    float* sS    = sm + 51200;   // [128]

    int tid = threadIdx.x;
    int bi  = blockIdx.x;
    int b = bi / NN, i = bi % NN;
    int vn = ev[b];
    bool pmi = (i < vn);
    int tx = tid & 15, ty = tid >> 4;
    int j0 = ty*8, k0 = tx*8;

    const float* erow = g_e + (size_t)bi*NN*CD;
    for (int t = tid; t < NN*CD/4; t += 256) {
        ((float4*)sE)[t] = ((const float4*)erow)[t];
        ((float4*)sW)[t] = ((const float4*)Wl_e)[t];
    }
    __syncthreads();

    const float* hpi = g_hp + (size_t)bi*512;
    const float* hpb = g_hp + (size_t)b*NN*512;

    float acc[8][8];
    // ---- GEMM1: z / adj ----
#pragma unroll
    for (int r=0;r<8;++r)
#pragma unroll
        for (int c=0;c<8;++c) acc[r][c]=0.f;
    gemm_tile<128,128,128>(sE + j0*128, sW + k0, acc);
    {
        float hwl[8], w2[8];
#pragma unroll
        for (int c=0;c<8;++c) { hwl[c] = hpi[k0+c]; w2[c] = wl2[k0+c]; }
#pragma unroll
        for (int r=0;r<8;++r) {
            const float* hv = hpb + (size_t)(j0+r)*512 + 128;
            float part = 0.f;
#pragma unroll
            for (int c=0;c<8;++c) {
                float z = acc[r][c] + hwl[c] + hv[k0+c];
                z = fmaxf(z, 0.f);
                part = fmaf(z, w2[c], part);
            }
            sPart[(j0+r)*16 + tx] = part;
        }
    }
    __syncthreads();
    if (tid < NN) {
        float a = 0.f;
#pragma unroll
        for (int t=0;t<16;++t) a += sPart[tid*16 + t];
        a += bl2[0];
        bool pm = pmi && (tid < vn);
        sS[tid] = pm ? (1.f/(1.f + expf(-a))) : 0.f;
    }
    for (int t = tid; t < NN*CD/4; t += 256)
        ((float4*)sW)[t] = ((const float4*)Wm_e)[t];
    __syncthreads();

    // ---- GEMM2: m ----
#pragma unroll
    for (int r=0;r<8;++r)
#pragma unroll
        for (int c=0;c<8;++c) acc[r][c]=0.f;
    gemm_tile<128,128,128>(sE + j0*128, sW + k0, acc);
    {
        float hwm[8];
#pragma unroll
        for (int c=0;c<8;++c) hwm[c] = hpi[256 + k0 + c];
        float* mout = g_mbuf + (size_t)bi*NN*CD;
#pragma unroll
        for (int r=0;r<8;++r) {
            float sj = sS[j0+r];
            const float* hv = hpb + (size_t)(j0+r)*512 + 384;
            float v[8];
#pragma unroll
            for (int c=0;c<8;++c)
                v[c] = fmaxf(acc[r][c] + hwm[c] + hv[k0+c], 0.f) * sj;
            float4 v0 = {v[0],v[1],v[2],v[3]};
            float4 v1 = {v[4],v[5],v[6],v[7]};
            *(float4*)(sM + (j0+r)*CD + k0)     = v0;
            *(float4*)(sM + (j0+r)*CD + k0 + 4) = v1;
            *(float4*)(mout + (size_t)(j0+r)*CD + k0)     = v0;
            *(float4*)(mout + (size_t)(j0+r)*CD + k0 + 4) = v1;
        }
    }
    __syncthreads();

    // ---- GEMM3: E@Wu_e ----
    for (int t = tid; t < NN*CD/4; t += 256)
        ((float4*)sW)[t] = ((const float4*)Wu_e)[t];
    __syncthreads();
#pragma unroll
    for (int r=0;r<8;++r)
#pragma unroll
        for (int c=0;c<8;++c) acc[r][c]=0.f;
    gemm_tile<128,128,128>(sE + j0*128, sW + k0, acc);
    __syncthreads();
    for (int t = tid; t < NN*CD/4; t += 256)
        ((float4*)sW)[t] = ((const float4*)Wu_m)[t];
    __syncthreads();
    // ---- GEMM4: + sM@Wu_m ----
    gemm_tile<128,128,128>(sM + j0*128, sW + k0, acc);
    {
        float bur[8];
#pragma unroll
        for (int c=0;c<8;++c) bur[c] = bu[k0+c];
        float* eout = g_e + (size_t)bi*NN*CD;
#pragma unroll
        for (int r=0;r<8;++r) {
            bool pm = pmi && ((j0+r) < vn);
            float v[8];
#pragma unroll
            for (int c=0;c<8;++c) {
                float nv = fmaxf(acc[r][c] + bur[c], 0.f);
                v[c] = pm ? nv : sE[(j0+r)*CD + k0 + c];
            }
            float4 v0 = {v[0],v[1],v[2],v[3]};
            float4 v1 = {v[4],v[5],v[6],v[7]};
            *(float4*)(eout + (size_t)(j0+r)*CD + k0)     = v0;
            *(float4*)(eout + (size_t)(j0+r)*CD + k0 + 4) = v1;
        }
    }
}

// ---------------- ms = sum_i m[b,i,j,k]  (deterministic fixed-order) ----------
__global__ void k_reduce_ms() {
    int t = blockIdx.x * blockDim.x + threadIdx.x;
    if (t >= BB*NN*CD) return;
    int b  = t / (NN*CD);
    int jk = t % (NN*CD);
    const float* base = g_mbuf + (size_t)b*NN*NN*CD + jk;
    float s = 0.f;
#pragma unroll 4
    for (int i = 0; i < NN; ++i) s += base[(size_t)i*NN*CD];
    g_ms[t] = s;
}

// ---------------- GRU gate update ---------------------------------------------
__global__ void k_gru(const int* __restrict__ ev) {
    int t = blockIdx.x * blockDim.x + threadIdx.x;
    if (t >= BB*NN*CD) return;
    int row = t / CD, c = t % CD;
    int b = row / NN, n = row % NN;
    if (n >= ev[b]) return;
    const float* gi = g_gi + (size_t)row*384;
    const float* gh = g_gh + (size_t)row*384;
    float ir = gi[c], iz = gi[CD+c], in = gi[2*CD+c];
    float hr = gh[c], hz = gh[CD+c], hn = gh[2*CD+c];
    float r  = 1.f/(1.f + expf(-(ir+hr)));
    float z  = 1.f/(1.f + expf(-(iz+hz)));
    float nn = tanhf(in + r*hn);
    float hold = g_h[t];
    g_h[t] = (1.f - z)*nn + z*hold;
}

// ---------------- readout: pairwise MLP + masked scatter ----------------------
#define RO_SMEM_FLOATS (16384*3)
__global__ __launch_bounds__(256, 1)
void k_readout(const float* __restrict__ Wr1, const float* __restrict__ br1,
               const float* __restrict__ Wr2, const float* __restrict__ br2,
               const int* __restrict__ ev, float* __restrict__ out)
{
    extern __shared__ float sm[];
    float* sF = sm;            // 64 x 256 feat
    float* sW = sm + 16384;    // 64 x 256 weight chunk
    float* sH = sm + 32768;    // 64 x 256 hidden
    int tid = threadIdx.x;
    int b   = blockIdx.y;
    int p0  = blockIdx.x * 64;   // P = 8128 = 127 * 64, always full tile

    for (int t = tid; t < 64*64; t += 256) {   // 64 pairs x 64 float4
        int lp = t >> 6; int c = (t & 63) * 4;
        int p = p0 + lp;
        int iu = g_iu[p], ju = g_ju[p];
        const float* src = (c < 128)
            ? g_e + (((size_t)(b*NN + iu))*NN + ju)*CD + c
            : g_e + (((size_t)(b*NN + ju))*NN + iu)*CD + (c - 128);
        *(float4*)(sF + lp*256 + c) = *(const float4*)src;
    }

    int tx = tid & 31, ty = tid >> 5;
    int r0 = ty*8, k0 = tx*8;
    float acc[8][8];
#pragma unroll
    for (int r=0;r<8;++r)
#pragma unroll
        for (int c=0;c<8;++c) acc[r][c]=0.f;

    for (int cc = 0; cc < 4; ++cc) {
        __syncthreads();   // sF ready (cc=0) / previous chunk consumed (cc>0)
        for (int t = tid; t < 64*64; t += 256) {
            int rr = t >> 6; int c = (t & 63) * 4;
            *(float4*)(sW + rr*256 + c) = *(const float4*)(Wr1 + (size_t)(cc*64 + rr)*256 + c);
        }
        __syncthreads();
        gemm_tile<256,256,64>(sF + r0*256 + cc*64, sW + k0, acc);
    }
    __syncthreads();
#pragma unroll
    for (int r=0;r<8;++r)
#pragma unroll
        for (int c=0;c<8;++c)
            sH[(r0+r)*256 + k0 + c] = fmaxf(acc[r][c] + br1[k0+c], 0.f);
    __syncthreads();

    int vn = ev[b];
    for (int o = tid; o < 64*10; o += 256) {
        int lp = o / 10, t5 = o % 10;
        const float* hrow = sH + lp*256;
        float s = br2[t5];
#pragma unroll 4
        for (int c = 0; c < 256; ++c) s = fmaf(hrow[c], Wr2[c*10 + t5], s);
        int p = p0 + lp;
        int iu = g_iu[p], ju = g_ju[p];
        if (ju < vn) {
            int idx = iu*vn - iu*(iu+1)/2 + (ju - iu - 1);
            out[(((size_t)b*5 + (t5 >> 1))*PP + idx)*2 + (t5 & 1)] = s;
        }
    }
}

// ---------------- host orchestration ------------------------------------------
extern "C" void kernel_launch(void* const* d_in, const int* in_sizes, int n_in,
                              void* d_out, int out_size) {
    const int*   edge_ids      = (const int*)  d_in[0];
    const float* node_features = (const float*)d_in[1];
    const int*   ev            = (const int*)  d_in[3];
    const float* emb           = (const float*)d_in[4];
    const float* Wl_e = (const float*)d_in[5];
    const float* Wl_w = (const float*)d_in[6];
    const float* Wl_v = (const float*)d_in[7];
    const float* bl1  = (const float*)d_in[8];
    const float* wl2  = (const float*)d_in[9];
    const float* bl2  = (const float*)d_in[10];
    const float* Wm_w = (const float*)d_in[11];
    const float* Wm_v = (const float*)d_in[12];
    const float* Wm_e = (const float*)d_in[13];
    const float* bm   = (const float*)d_in[14];
    const float* Wu_e = (const float*)d_in[15];
    const float* Wu_m = (const float*)d_in[16];
    const float* bu   = (const float*)d_in[17];
    const float* W_ih = (const float*)d_in[18];
    const float* W_hh = (const float*)d_in[19];
    const float* b_ih = (const float*)d_in[20];
    const float* b_hh = (const float*)d_in[21];
    const float* Wr1  = (const float*)d_in[22];
    const float* br1  = (const float*)d_in[23];
    const float* Wr2  = (const float*)d_in[24];
    const float* br2  = (const float*)d_in[25];

    cudaFuncSetAttribute(k_edge,    cudaFuncAttributeMaxDynamicSharedMemorySize,
                         EDGE_SMEM_FLOATS * (int)sizeof(float));
    cudaFuncSetAttribute(k_readout, cudaFuncAttributeMaxDynamicSharedMemorySize,
                         RO_SMEM_FLOATS * (int)sizeof(float));

    void *p_h, *p_hp, *p_ms, *p_gi, *p_gh;
    cudaGetSymbolAddress(&p_h,  g_h);
    cudaGetSymbolAddress(&p_hp, g_hp);
    cudaGetSymbolAddress(&p_ms, g_ms);
    cudaGetSymbolAddress(&p_gi, g_gi);
    cudaGetSymbolAddress(&p_gh, g_gh);

    k_init_e<<<65536, 256>>>(edge_ids, emb);
    k_copy_h<<<(BB*NN*CD/4 + 255)/256, 256>>>(node_features);
    k_init_pairs<<<(NN*NN + 255)/256, 256>>>();

    for (int r = 0; r < RNDS; ++r) {
        // node projections: [hwl(+bl1) | hvl | hwm(+bm) | hvm]
        k_rowgemm<<<BB*NN/32, 128>>>((const float*)p_h, Wl_w, bl1,     (float*)p_hp, 128, 512, 0);
        k_rowgemm<<<BB*NN/32, 128>>>((const float*)p_h, Wl_v, nullptr, (float*)p_hp, 128, 512, 128);
        k_rowgemm<<<BB*NN/32, 128>>>((const float*)p_h, Wm_w, bm,      (float*)p_hp, 128, 512, 256);
        k_rowgemm<<<BB*NN/32, 128>>>((const float*)p_h, Wm_v, nullptr, (float*)p_hp, 128, 512, 384);

        k_edge<<<BB*NN, 256, EDGE_SMEM_FLOATS * sizeof(float)>>>(
            Wl_e, Wm_e, Wu_e, Wu_m, wl2, bl2, bu, ev);

        k_reduce_ms<<<(BB*NN*CD + 255)/256, 256>>>();

        k_rowgemm<<<BB*NN/32, 384>>>((const float*)p_ms, W_ih, b_ih, (float*)p_gi, 384, 384, 0);
        k_rowgemm<<<BB*NN/32, 384>>>((const float*)p_h,  W_hh, b_hh, (float*)p_gh, 384, 384, 0);
        k_gru<<<(BB*NN*CD + 255)/256, 256>>>(ev);
    }

    cudaMemsetAsync(d_out, 0, (size_t)out_size * sizeof(float));
    k_readout<<<dim3(PP/64, BB), 256, RO_SMEM_FLOATS * sizeof(float)>>>(
        Wr1, br1, Wr2, br2, ev, (float*)d_out);
}

// round 2
// speedup vs baseline: 1.0076x; 1.0076x over previous
#include <cuda_runtime.h>
#include <math.h>
#include <stdint.h>

#define BB 32
#define NN 128
#define CD 128
#define PP 8128
#define RNDS 3

// ---------------- persistent device scratch (rewritten fully every launch) ----
__device__ float g_e   [(size_t)BB*NN*NN*CD];   // 256 MB edge features
__device__ float g_mbuf[(size_t)BB*NN*NN*CD];   // 256 MB messages (pre-reduction)
__device__ float g_h   [BB*NN*CD];
__device__ float g_hp  [BB*NN*512];             // [hwl | hvl | hwm | hvm]
__device__ float g_ms  [BB*NN*CD];
__device__ float g_gi  [BB*NN*384];
__device__ float g_gh  [BB*NN*384];
__device__ int   g_iu  [PP];
__device__ int   g_ju  [PP];

// ---------------- init kernels ------------------------------------------------
__global__ void k_init_e(const int* __restrict__ eids, const float* __restrict__ emb) {
    size_t t = (size_t)blockIdx.x * blockDim.x + threadIdx.x;   // over B*N*N*(CD/4)
    size_t total = (size_t)BB*NN*NN*(CD/4);
    if (t >= total) return;
    size_t edge = t >> 5;        // CD/4 = 32 float4 per edge
    int c4 = (int)(t & 31);
    int id = eids[edge];
    ((float4*)g_e)[t] = ((const float4*)emb)[id*(CD/4) + c4];
}

__global__ void k_copy_h(const float* __restrict__ nf) {
    int t = blockIdx.x * blockDim.x + threadIdx.x;
    if (t < BB*NN*CD/4) ((float4*)g_h)[t] = ((const float4*)nf)[t];
}

__global__ void k_init_pairs() {
    int t = blockIdx.x * blockDim.x + threadIdx.x;
    if (t >= NN*NN) return;
    int i = t / NN, j = t % NN;
    if (j > i) {
        int p = i*(NN-1) - i*(i-1)/2 + (j - i - 1);
        g_iu[p] = i; g_ju[p] = j;
    }
}

// ---------------- small row-block GEMM: C[rows,outC] = A[rows,128] @ W + bias --
__global__ void k_rowgemm(const float* __restrict__ A, const float* __restrict__ W,
                          const float* __restrict__ bias, float* __restrict__ C,
                          int outC, int ldC, int colOff) {
    __shared__ float sA[32*CD];
    int row0 = blockIdx.x * 32;
    for (int t = threadIdx.x; t < 32*CD; t += blockDim.x)
        sA[t] = A[(size_t)row0*CD + t];
    __syncthreads();
    int col = threadIdx.x;
    if (col >= outC) return;
    float acc[32];
#pragma unroll
    for (int r = 0; r < 32; ++r) acc[r] = 0.f;
    for (int c = 0; c < CD; ++c) {
        float w = W[c*outC + col];
#pragma unroll
        for (int r = 0; r < 32; ++r) acc[r] = fmaf(sA[r*CD + c], w, acc[r]);
    }
    float bv = bias ? bias[col] : 0.f;
    for (int r = 0; r < 32; ++r)
        C[(size_t)(row0 + r)*ldC + colOff + col] = acc[r] + bv;
}

// ---------------- shared 8x8 register-tile GEMM core ---------------------------
template<int LDA, int LDB, int KSTEPS>
__device__ __forceinline__ void gemm_tile(const float* __restrict__ pA,   // &sA[r0*LDA + cbeg]
                                          const float* __restrict__ pB,   // &sB[0*LDB + k0]
                                          float acc[8][8]) {
#pragma unroll 2
    for (int c0 = 0; c0 < KSTEPS; c0 += 4) {
        float4 a4[8];
#pragma unroll
        for (int r = 0; r < 8; ++r)
            a4[r] = *(const float4*)(pA + r*LDA + c0);
#pragma unroll
        for (int cs = 0; cs < 4; ++cs) {
            float4 b0 = *(const float4*)(pB + (size_t)(c0 + cs)*LDB);
            float4 b1 = *(const float4*)(pB + (size_t)(c0 + cs)*LDB + 4);
            float bb[8] = {b0.x,b0.y,b0.z,b0.w,b1.x,b1.y,b1.z,b1.w};
#pragma unroll
            for (int r = 0; r < 8; ++r) {
                float av = (cs==0) ? a4[r].x : (cs==1) ? a4[r].y : (cs==2) ? a4[r].z : a4[r].w;
#pragma unroll
                for (int c = 0; c < 8; ++c)
                    acc[r][c] = fmaf(av, bb[c], acc[r][c]);
            }
        }
    }
}

// ---------------- the fused per-edge-row kernel (hot loop) ---------------------
// CTA = (b, i). E tile 128x128 in smem; 4 GEMMs:
//  1) E@Wl_e -> z -> adj -> s          2) E@Wm_e -> m (masked*scaled) -> sM, g_mbuf
//  3) E@Wu_e (+)  4) sM@Wu_m  -> e_new = pm ? relu(.+bu) : e_old
#define EDGE_SMEM_FLOATS (16384*3 + 2048 + 128)
__global__ __launch_bounds__(256, 1)
void k_edge(const float* __restrict__ Wl_e, const float* __restrict__ Wm_e,
            const float* __restrict__ Wu_e, const float* __restrict__ Wu_m,
            const float* __restrict__ wl2,  const float* __restrict__ bl2,
            const float* __restrict__ bu,   const int* __restrict__ ev)
{
    extern __shared__ float sm[];
    float* sE    = sm;
    float* sW    = sm + 16384;
    float* sM    = sm + 32768;
    float* sPart = sm + 49152;   // [128][16] adj partials (deterministic reduce)
    float* sS    = sm + 51200;   // [128]

    int tid = threadIdx.x;
    int bi  = blockIdx.x;
    int b = bi / NN, i = bi % NN;
    int vn = ev[b];
    bool pmi = (i < vn);
    int tx = tid & 15, ty = tid >> 4;
    int j0 = ty*8, k0 = tx*8;

    const float* erow = g_e + (size_t)bi*NN*CD;
    for (int t = tid; t < NN*CD/4; t += 256) {
        ((float4*)sE)[t] = ((const float4*)erow)[t];
        ((float4*)sW)[t] = ((const float4*)Wl_e)[t];
    }
    __syncthreads();

    const float* hpi = g_hp + (size_t)bi*512;
    const float* hpb = g_hp + (size_t)b*NN*512;

    float acc[8][8];
    // ---- GEMM1: z / adj ----
#pragma unroll
    for (int r=0;r<8;++r)
#pragma unroll
        for (int c=0;c<8;++c) acc[r][c]=0.f;
    gemm_tile<128,128,128>(sE + j0*128, sW + k0, acc);
    {
        float hwl[8], w2[8];
#pragma unroll
        for (int c=0;c<8;++c) { hwl[c] = hpi[k0+c]; w2[c] = wl2[k0+c]; }
#pragma unroll
        for (int r=0;r<8;++r) {
            const float* hv = hpb + (size_t)(j0+r)*512 + 128;
            float part = 0.f;
#pragma unroll
            for (int c=0;c<8;++c) {
                float z = acc[r][c] + hwl[c] + hv[k0+c];
                z = fmaxf(z, 0.f);
                part = fmaf(z, w2[c], part);
            }
            sPart[(j0+r)*16 + tx] = part;
        }
    }
    __syncthreads();
    if (tid < NN) {
        float a = 0.f;
#pragma unroll
        for (int t=0;t<16;++t) a += sPart[tid*16 + t];
        a += bl2[0];
        bool pm = pmi && (tid < vn);
        sS[tid] = pm ? (1.f/(1.f + expf(-a))) : 0.f;
    }
    for (int t = tid; t < NN*CD/4; t += 256)
        ((float4*)sW)[t] = ((const float4*)Wm_e)[t];
    __syncthreads();

    // ---- GEMM2: m ----
#pragma unroll
    for (int r=0;r<8;++r)
#pragma unroll
        for (int c=0;c<8;++c) acc[r][c]=0.f;
    gemm_tile<128,128,128>(sE + j0*128, sW + k0, acc);
    {
        float hwm[8];
#pragma unroll
        for (int c=0;c<8;++c) hwm[c] = hpi[256 + k0 + c];
        float* mout = g_mbuf + (size_t)bi*NN*CD;
#pragma unroll
        for (int r=0;r<8;++r) {
            float sj = sS[j0+r];
            const float* hv = hpb + (size_t)(j0+r)*512 + 384;
            float v[8];
#pragma unroll
            for (int c=0;c<8;++c)
                v[c] = fmaxf(acc[r][c] + hwm[c] + hv[k0+c], 0.f) * sj;
            float4 v0 = {v[0],v[1],v[2],v[3]};
            float4 v1 = {v[4],v[5],v[6],v[7]};
            *(float4*)(sM + (j0+r)*CD + k0)     = v0;
            *(float4*)(sM + (j0+r)*CD + k0 + 4) = v1;
            *(float4*)(mout + (size_t)(j0+r)*CD + k0)     = v0;
            *(float4*)(mout + (size_t)(j0+r)*CD + k0 + 4) = v1;
        }
    }
    __syncthreads();

    // ---- GEMM3: E@Wu_e ----
    for (int t = tid; t < NN*CD/4; t += 256)
        ((float4*)sW)[t] = ((const float4*)Wu_e)[t];
    __syncthreads();
#pragma unroll
    for (int r=0;r<8;++r)
#pragma unroll
        for (int c=0;c<8;++c) acc[r][c]=0.f;
    gemm_tile<128,128,128>(sE + j0*128, sW + k0, acc);
    __syncthreads();
    for (int t = tid; t < NN*CD/4; t += 256)
        ((float4*)sW)[t] = ((const float4*)Wu_m)[t];
    __syncthreads();
    // ---- GEMM4: + sM@Wu_m ----
    gemm_tile<128,128,128>(sM + j0*128, sW + k0, acc);
    {
        float bur[8];
#pragma unroll
        for (int c=0;c<8;++c) bur[c] = bu[k0+c];
        float* eout = g_e + (size_t)bi*NN*CD;
#pragma unroll
        for (int r=0;r<8;++r) {
            bool pm = pmi && ((j0+r) < vn);
            float v[8];
#pragma unroll
            for (int c=0;c<8;++c) {
                float nv = fmaxf(acc[r][c] + bur[c], 0.f);
                v[c] = pm ? nv : sE[(j0+r)*CD + k0 + c];
            }
            float4 v0 = {v[0],v[1],v[2],v[3]};
            float4 v1 = {v[4],v[5],v[6],v[7]};
            *(float4*)(eout + (size_t)(j0+r)*CD + k0)     = v0;
            *(float4*)(eout + (size_t)(j0+r)*CD + k0 + 4) = v1;
        }
    }
}

// ---------------- ms = sum_i m[b,i,j,k]  (deterministic fixed-order) ----------
__global__ void k_reduce_ms() {
    int t = blockIdx.x * blockDim.x + threadIdx.x;
    if (t >= BB*NN*CD) return;
    int b  = t / (NN*CD);
    int jk = t % (NN*CD);
    const float* base = g_mbuf + (size_t)b*NN*NN*CD + jk;
    float s = 0.f;
#pragma unroll 4
    for (int i = 0; i < NN; ++i) s += base[(size_t)i*NN*CD];
    g_ms[t] = s;
}

// ---------------- GRU gate update ---------------------------------------------
__global__ void k_gru(const int* __restrict__ ev) {
    int t = blockIdx.x * blockDim.x + threadIdx.x;
    if (t >= BB*NN*CD) return;
    int row = t / CD, c = t % CD;
    int b = row / NN, n = row % NN;
    if (n >= ev[b]) return;
    const float* gi = g_gi + (size_t)row*384;
    const float* gh = g_gh + (size_t)row*384;
    float ir = gi[c], iz = gi[CD+c], in = gi[2*CD+c];
    float hr = gh[c], hz = gh[CD+c], hn = gh[2*CD+c];
    float r  = 1.f/(1.f + expf(-(ir+hr)));
    float z  = 1.f/(1.f + expf(-(iz+hz)));
    float nn = tanhf(in + r*hn);
    float hold = g_h[t];
    g_h[t] = (1.f - z)*nn + z*hold;
}

// ---------------- readout: pairwise MLP + masked scatter ----------------------
#define RO_SMEM_FLOATS (16384*3)
__global__ __launch_bounds__(256, 1)
void k_readout(const float* __restrict__ Wr1, const float* __restrict__ br1,
               const float* __restrict__ Wr2, const float* __restrict__ br2,
               const int* __restrict__ ev, float* __restrict__ out)
{
    extern __shared__ float sm[];
    float* sF = sm;            // 64 x 256 feat
    float* sW = sm + 16384;    // 64 x 256 weight chunk
    float* sH = sm + 32768;    // 64 x 256 hidden
    int tid = threadIdx.x;
    int b   = blockIdx.y;
    int p0  = blockIdx.x * 64;   // P = 8128 = 127 * 64, always full tile

    for (int t = tid; t < 64*64; t += 256) {   // 64 pairs x 64 float4
        int lp = t >> 6; int c = (t & 63) * 4;
        int p = p0 + lp;
        int iu = g_iu[p], ju = g_ju[p];
        const float* src = (c < 128)
            ? g_e + (((size_t)(b*NN + iu))*NN + ju)*CD + c
            : g_e + (((size_t)(b*NN + ju))*NN + iu)*CD + (c - 128);
        *(float4*)(sF + lp*256 + c) = *(const float4*)src;
    }

    int tx = tid & 31, ty = tid >> 5;
    int r0 = ty*8, k0 = tx*8;
    float acc[8][8];
#pragma unroll
    for (int r=0;r<8;++r)
#pragma unroll
        for (int c=0;c<8;++c) acc[r][c]=0.f;

    for (int cc = 0; cc < 4; ++cc) {
        __syncthreads();   // sF ready (cc=0) / previous chunk consumed (cc>0)
        for (int t = tid; t < 64*64; t += 256) {
            int rr = t >> 6; int c = (t & 63) * 4;
            *(float4*)(sW + rr*256 + c) = *(const float4*)(Wr1 + (size_t)(cc*64 + rr)*256 + c);
        }
        __syncthreads();
        gemm_tile<256,256,64>(sF + r0*256 + cc*64, sW + k0, acc);
    }
    __syncthreads();
#pragma unroll
    for (int r=0;r<8;++r)
#pragma unroll
        for (int c=0;c<8;++c)
            sH[(r0+r)*256 + k0 + c] = fmaxf(acc[r][c] + br1[k0+c], 0.f);
    __syncthreads();

    int vn = ev[b];
    for (int o = tid; o < 64*10; o += 256) {
        int lp = o / 10, t5 = o % 10;
        const float* hrow = sH + lp*256;
        float s = br2[t5];
#pragma unroll 4
        for (int c = 0; c < 256; ++c) s = fmaf(hrow[c], Wr2[c*10 + t5], s);
        int p = p0 + lp;
        int iu = g_iu[p], ju = g_ju[p];
        if (ju < vn) {
            int idx = iu*vn - iu*(iu+1)/2 + (ju - iu - 1);
            out[(((size_t)b*5 + (t5 >> 1))*PP + idx)*2 + (t5 & 1)] = s;
        }
    }
}

// ---------------- host orchestration ------------------------------------------
extern "C" void kernel_launch(void* const* d_in, const int* in_sizes, int n_in,
                              void* d_out, int out_size) {
    const int*   edge_ids      = (const int*)  d_in[0];
    const float* node_features = (const float*)d_in[1];
    const int*   ev            = (const int*)  d_in[3];
    const float* emb           = (const float*)d_in[4];
    const float* Wl_e = (const float*)d_in[5];
    const float* Wl_w = (const float*)d_in[6];
    const float* Wl_v = (const float*)d_in[7];
    const float* bl1  = (const float*)d_in[8];
    const float* wl2  = (const float*)d_in[9];
    const float* bl2  = (const float*)d_in[10];
    const float* Wm_w = (const float*)d_in[11];
    const float* Wm_v = (const float*)d_in[12];
    const float* Wm_e = (const float*)d_in[13];
    const float* bm   = (const float*)d_in[14];
    const float* Wu_e = (const float*)d_in[15];
    const float* Wu_m = (const float*)d_in[16];
    const float* bu   = (const float*)d_in[17];
    const float* W_ih = (const float*)d_in[18];
    const float* W_hh = (const float*)d_in[19];
    const float* b_ih = (const float*)d_in[20];
    const float* b_hh = (const float*)d_in[21];
    const float* Wr1  = (const float*)d_in[22];
    const float* br1  = (const float*)d_in[23];
    const float* Wr2  = (const float*)d_in[24];
    const float* br2  = (const float*)d_in[25];

    cudaFuncSetAttribute(k_edge,    cudaFuncAttributeMaxDynamicSharedMemorySize,
                         EDGE_SMEM_FLOATS * (int)sizeof(float));
    cudaFuncSetAttribute(k_readout, cudaFuncAttributeMaxDynamicSharedMemorySize,
                         RO_SMEM_FLOATS * (int)sizeof(float));

    void *p_h, *p_hp, *p_ms, *p_gi, *p_gh;
    cudaGetSymbolAddress(&p_h,  g_h);
    cudaGetSymbolAddress(&p_hp, g_hp);
    cudaGetSymbolAddress(&p_ms, g_ms);
    cudaGetSymbolAddress(&p_gi, g_gi);
    cudaGetSymbolAddress(&p_gh, g_gh);

    k_init_e<<<65536, 256>>>(edge_ids, emb);
    k_copy_h<<<(BB*NN*CD/4 + 255)/256, 256>>>(node_features);
    k_init_pairs<<<(NN*NN + 255)/256, 256>>>();

    for (int r = 0; r < RNDS; ++r) {
        // node projections: [hwl(+bl1) | hvl | hwm(+bm) | hvm]
        k_rowgemm<<<BB*NN/32, 128>>>((const float*)p_h, Wl_w, bl1,     (float*)p_hp, 128, 512, 0);
        k_rowgemm<<<BB*NN/32, 128>>>((const float*)p_h, Wl_v, nullptr, (float*)p_hp, 128, 512, 128);
        k_rowgemm<<<BB*NN/32, 128>>>((const float*)p_h, Wm_w, bm,      (float*)p_hp, 128, 512, 256);
        k_rowgemm<<<BB*NN/32, 128>>>((const float*)p_h, Wm_v, nullptr, (float*)p_hp, 128, 512, 384);

        k_edge<<<BB*NN, 256, EDGE_SMEM_FLOATS * sizeof(float)>>>(
            Wl_e, Wm_e, Wu_e, Wu_m, wl2, bl2, bu, ev);

        k_reduce_ms<<<(BB*NN*CD + 255)/256, 256>>>();

        k_rowgemm<<<BB*NN/32, 384>>>((const float*)p_ms, W_ih, b_ih, (float*)p_gi, 384, 384, 0);
        k_rowgemm<<<BB*NN/32, 384>>>((const float*)p_h,  W_hh, b_hh, (float*)p_gh, 384, 384, 0);
        k_gru<<<(BB*NN*CD + 255)/256, 256>>>(ev);
    }

    cudaMemsetAsync(d_out, 0, (size_t)out_size * sizeof(float));
    k_readout<<<dim3(PP/64, BB), 256, RO_SMEM_FLOATS * sizeof(float)>>>(
        Wr1, br1, Wr2, br2, ev, (float*)d_out);
}